// round 14
// baseline (speedup 1.0000x reference)
#include <cuda_runtime.h>

// SKA: out[b, g*32+c, h, w] = sum_{di,dj} x[b, g*32+c, h+di-2, w+dj-2] * w[b, g, di*5+dj, h, w]
// x [8,256,64,64] f32, w [8,8,25,64,64] f32, out [8,256,64,64] f32.
//
// R9 reference structure: thread = 4px x 4ch x 2rows; warp = 16wq x 2 slots;
// x window from ONE aligned LDG.128 + width-16 shfl halos; w tile [25][4][64]
// in smem with broadcast LDS.128; immediate offsets; 3 CTAs/SM.
// R14 single delta: horizontal edge handling folded into the weights — the
// fill loop zeroes boundary tap components inline (dj0:cols{0,1}, dj1:{0},
// dj3:{63}, dj4:{62,63}) so the main loop has NO edge selects; shfl
// own-value garbage at segment boundaries is multiplied by zero.

#define B_  8
#define C_  256
#define H_  64
#define W_  64
#define G_  8
#define CG_ 32
#define HW_ (H_ * W_)

__global__ __launch_bounds__(256, 3)
void SKA_60387240182286_kernel(const float* __restrict__ x,
                               const float* __restrict__ wgt,
                               float* __restrict__ out)
{
    __shared__ float ws[25 * 4 * W_];     // [k][4 rows][64] = 25.6 KB

    const int tid  = threadIdx.x;
    const int lane = tid & 31;
    const int warp = tid >> 5;            // 0..7
    const int wq      = lane & 15;        // 0..15: 4-wide pixel group
    const int slot_lo = lane >> 4;        // 0..1: shfl segment = channel-slot bit
    const int slot = slot_lo + 2 * (warp & 3);  // 0..7: 4-channel slot
    const int hsub = warp >> 2;           // 0..1: which hpair of the block

    const int bg  = blockIdx.x;           // b*8 + g
    const int b   = bg >> 3;
    const int g   = bg & 7;
    const int h0b = blockIdx.y * 4;       // block covers 4 output rows
    const int h0  = h0b + hsub * 2;       // this warp's 2-row base
    const int w0  = wq * 4;
    const int c0  = g * CG_ + slot * 4;

    // ---- stage w tile: rows h0b..h0b+3, all 25 taps, with inline boundary
    // zeroing (tap (di,dj) at pixel col is invalid iff col+dj-2 outside [0,63])
    {
        const float* wsrc = wgt + ((size_t)bg * 25 * H_ + h0b) * W_;
        float4* wsv = (float4*)ws;
#pragma unroll
        for (int i = tid; i < 1600; i += 256) {     // 1600 float4
            const int k   = i >> 6;                  // tap: 64 f4 per tap (4 rows x 16)
            const int rem = i & 63;
            const int c4  = (rem & 15) * 4;          // first pixel col of this float4
            float4 v = *(const float4*)(wsrc + (size_t)k * HW_ +
                                        (rem >> 4) * W_ + c4);
            const int dj = k - (k / 5) * 5;          // k % 5
            if (c4 == 0) {
                if (dj == 0) { v.x = 0.f; v.y = 0.f; }
                if (dj == 1) { v.x = 0.f; }
            }
            if (c4 == 60) {
                if (dj == 3) { v.w = 0.f; }
                if (dj == 4) { v.z = 0.f; v.w = 0.f; }
            }
            wsv[i] = v;
        }
    }
    __syncthreads();

    const float* xb  = x + (((size_t)(b * C_ + c0)) * H_ + (h0 - 2)) * W_ + w0;
    const float* wsb = ws + (hsub * 2) * W_ + w0;   // + (k*4+rr)*W_ immediates

    float acc[2][4][4];                   // [rr][c][px]
#pragma unroll
    for (int r = 0; r < 2; ++r)
#pragma unroll
        for (int c = 0; c < 4; ++c) {
            acc[r][c][0] = 0.f; acc[r][c][1] = 0.f;
            acc[r][c][2] = 0.f; acc[r][c][3] = 0.f;
        }

    const float4 z4 = make_float4(0.f, 0.f, 0.f, 0.f);

#pragma unroll
    for (int hi = 0; hi < 6; ++hi) {                // x row hy = h0 - 2 + hi
        const int hy = h0 - 2 + hi;
        const bool rv = (hy >= 0) && (hy < H_);     // warp-uniform (load safety)

        // window xw[c][0..7] covers cols [w0-2 .. w0+5]; NO edge selects —
        // out-of-image positions are killed by zeroed weight taps.
        float xw[4][8];
#pragma unroll
        for (int c = 0; c < 4; ++c) {
            const float4 m = rv ? *(const float4*)(xb + c * HW_ + hi * W_) : z4;
            xw[c][0] = __shfl_up_sync(0xFFFFFFFFu, m.z, 1, 16);
            xw[c][1] = __shfl_up_sync(0xFFFFFFFFu, m.w, 1, 16);
            xw[c][2] = m.x; xw[c][3] = m.y; xw[c][4] = m.z; xw[c][5] = m.w;
            xw[c][6] = __shfl_down_sync(0xFFFFFFFFu, m.x, 1, 16);
            xw[c][7] = __shfl_down_sync(0xFFFFFFFFu, m.y, 1, 16);
        }

        // x row hi feeds output row rr where di = hi - rr in [0,4]
#pragma unroll
        for (int rr = 0; rr < 2; ++rr) {
            const int di = hi - rr;
            if (di < 0 || di > 4) continue;         // compile-time prune
#pragma unroll
            for (int dj = 0; dj < 5; ++dj) {
                const int k = di * 5 + dj;
                const float4 wv = *(const float4*)(wsb + (k * 4 + rr) * W_);
#pragma unroll
                for (int c = 0; c < 4; ++c) {
                    acc[rr][c][0] = fmaf(xw[c][dj + 0], wv.x, acc[rr][c][0]);
                    acc[rr][c][1] = fmaf(xw[c][dj + 1], wv.y, acc[rr][c][1]);
                    acc[rr][c][2] = fmaf(xw[c][dj + 2], wv.z, acc[rr][c][2]);
                    acc[rr][c][3] = fmaf(xw[c][dj + 3], wv.w, acc[rr][c][3]);
                }
            }
        }
    }

    float* ob = out + (((size_t)(b * C_ + c0)) * H_ + h0) * W_ + w0;
#pragma unroll
    for (int rr = 0; rr < 2; ++rr)
#pragma unroll
        for (int c = 0; c < 4; ++c) {
            *(float4*)(ob + c * HW_ + rr * W_) =
                make_float4(acc[rr][c][0], acc[rr][c][1],
                            acc[rr][c][2], acc[rr][c][3]);
        }
}

extern "C" void kernel_launch(void* const* d_in, const int* in_sizes, int n_in,
                              void* d_out, int out_size)
{
    const float* x   = (const float*)d_in[0];
    const float* wgt = (const float*)d_in[1];
    float* out = (float*)d_out;

    dim3 grid(B_ * G_, H_ / 4);   // (64, 16) = 1024 blocks
    SKA_60387240182286_kernel<<<grid, 256>>>(x, wgt, out);
}

// round 15
// speedup vs baseline: 1.2649x; 1.2649x over previous
#include <cuda_runtime.h>

// SKA: out[b, g*32+c, h, w] = sum_{di,dj} x[b, g*32+c, h+di-2, w+dj-2] * w[b, g, di*5+dj, h, w]
// x [8,256,64,64] f32, w [8,8,25,64,64] f32, out [8,256,64,64] f32.
//
// R9's warp-level code EXACTLY (thread = 4px x 4ch x 2rows; warp = 16wq x 2
// slots; x window from ONE aligned LDG.128 + width-16 shfl halos + edge SELs;
// w tile in smem with broadcast LDS.128; immediate offsets), but block = 128
// threads covering 2 output rows (w tile [25][2][64] = 12.8 KB). Same 24
// warps/SM (6 CTAs x 4 warps); finer wave granularity (4096 blocks -> 4.6
// waves) and a 4-warp barrier instead of 8.

#define B_  8
#define C_  256
#define H_  64
#define W_  64
#define G_  8
#define CG_ 32
#define HW_ (H_ * W_)

__global__ __launch_bounds__(128, 6)
void SKA_60387240182286_kernel(const float* __restrict__ x,
                               const float* __restrict__ wgt,
                               float* __restrict__ out)
{
    __shared__ float ws[25 * 2 * W_];     // [k][2 rows][64] = 12.8 KB

    const int tid  = threadIdx.x;
    const int lane = tid & 31;
    const int warp = tid >> 5;            // 0..3
    const int wq      = lane & 15;        // 0..15: 4-wide pixel group
    const int slot_lo = lane >> 4;        // 0..1: shfl segment = channel-slot bit
    const int slot = slot_lo + 2 * warp;  // 0..7: 4-channel slot

    const int bg = blockIdx.x;            // b*8 + g
    const int b  = bg >> 3;
    const int g  = bg & 7;
    const int h0 = blockIdx.y * 2;        // block covers 2 output rows
    const int w0 = wq * 4;
    const int c0 = g * CG_ + slot * 4;

    // ---- stage w tile: rows h0..h0+1, all 25 taps
    {
        const float* wsrc = wgt + ((size_t)bg * 25 * H_ + h0) * W_;
        float4* wsv = (float4*)ws;
#pragma unroll
        for (int i = tid; i < 800; i += 128) {      // 800 float4
            const int k   = i >> 5;                  // 32 f4 per tap (2 rows x 16)
            const int rem = i & 31;
            wsv[i] = *(const float4*)(wsrc + (size_t)k * HW_ +
                                      (rem >> 4) * W_ + (rem & 15) * 4);
        }
    }
    __syncthreads();

    const float* xb  = x + (((size_t)(b * C_ + c0)) * H_ + (h0 - 2)) * W_ + w0;
    const float* wsb = ws + w0;           // + (k*2+rr)*W_ immediates

    float acc[2][4][4];                   // [rr][c][px]
#pragma unroll
    for (int r = 0; r < 2; ++r)
#pragma unroll
        for (int c = 0; c < 4; ++c) {
            acc[r][c][0] = 0.f; acc[r][c][1] = 0.f;
            acc[r][c][2] = 0.f; acc[r][c][3] = 0.f;
        }

    const float4 z4 = make_float4(0.f, 0.f, 0.f, 0.f);
    const bool le = (wq == 0);
    const bool re = (wq == 15);

#pragma unroll
    for (int hi = 0; hi < 6; ++hi) {                // x row hy = h0 - 2 + hi
        const int hy = h0 - 2 + hi;
        const bool rv = (hy >= 0) && (hy < H_);     // warp-uniform

        // window xw[c][0..7] covers cols [w0-2 .. w0+5]
        float xw[4][8];
#pragma unroll
        for (int c = 0; c < 4; ++c) {
            const float4 m = rv ? *(const float4*)(xb + c * HW_ + hi * W_) : z4;
            const float lz = __shfl_up_sync(0xFFFFFFFFu, m.z, 1, 16);
            const float lw = __shfl_up_sync(0xFFFFFFFFu, m.w, 1, 16);
            const float rx = __shfl_down_sync(0xFFFFFFFFu, m.x, 1, 16);
            const float ry = __shfl_down_sync(0xFFFFFFFFu, m.y, 1, 16);
            xw[c][0] = le ? 0.f : lz;
            xw[c][1] = le ? 0.f : lw;
            xw[c][2] = m.x; xw[c][3] = m.y; xw[c][4] = m.z; xw[c][5] = m.w;
            xw[c][6] = re ? 0.f : rx;
            xw[c][7] = re ? 0.f : ry;
        }

        // x row hi feeds output row rr where di = hi - rr in [0,4]
#pragma unroll
        for (int rr = 0; rr < 2; ++rr) {
            const int di = hi - rr;
            if (di < 0 || di > 4) continue;         // compile-time prune
#pragma unroll
            for (int dj = 0; dj < 5; ++dj) {
                const int k = di * 5 + dj;
                const float4 wv = *(const float4*)(wsb + (k * 2 + rr) * W_);
#pragma unroll
                for (int c = 0; c < 4; ++c) {
                    // out px p (col w0+p), tap dj -> window idx p+dj
                    acc[rr][c][0] = fmaf(xw[c][dj + 0], wv.x, acc[rr][c][0]);
                    acc[rr][c][1] = fmaf(xw[c][dj + 1], wv.y, acc[rr][c][1]);
                    acc[rr][c][2] = fmaf(xw[c][dj + 2], wv.z, acc[rr][c][2]);
                    acc[rr][c][3] = fmaf(xw[c][dj + 3], wv.w, acc[rr][c][3]);
                }
            }
        }
    }

    float* ob = out + (((size_t)(b * C_ + c0)) * H_ + h0) * W_ + w0;
#pragma unroll
    for (int rr = 0; rr < 2; ++rr)
#pragma unroll
        for (int c = 0; c < 4; ++c) {
            *(float4*)(ob + c * HW_ + rr * W_) =
                make_float4(acc[rr][c][0], acc[rr][c][1],
                            acc[rr][c][2], acc[rr][c][3]);
        }
}

extern "C" void kernel_launch(void* const* d_in, const int* in_sizes, int n_in,
                              void* d_out, int out_size)
{
    const float* x   = (const float*)d_in[0];
    const float* wgt = (const float*)d_in[1];
    float* out = (float*)d_out;

    dim3 grid(B_ * G_, H_ / 2);   // (64, 32) = 4096 blocks of 128 threads
    SKA_60387240182286_kernel<<<grid, 128>>>(x, wgt, out);
}